// round 15
// baseline (speedup 1.0000x reference)
#include <cuda_runtime.h>
#include <cuda_bf16.h>
#include <math.h>

// ---------------- problem dims ----------------
#define NB 2
#define HH 64
#define WW 64
#define DD 256
#define SS 16
#define NHD 4
#define HDIM 64
#define MLPH 1024
#define NPOS (NB*HH*WW)          // 8192
#define NKV  (NPOS*SS)           // 131072

// ---------------- scratch (device globals; no allocations allowed) -------
__device__ __align__(256) float g_off [(size_t)NPOS * 32];    // transformed offsets
__device__ __align__(256) float g_Wqk [DD * 4 * DD];          // folded Wq·Wk^T [256,1024]
__device__ __align__(256) float g_Wvo [4 * DD * DD];          // folded Wv·Wo   [1024,256]
__device__ __align__(256) float g_bqk [4 * DD];               // folded bq·Wk^T [1024]
__device__ __align__(256) float g_bvo [DD];                   // folded bo+bv·Wo [256]
__device__ __align__(256) float g_qk  [(size_t)NPOS * 4 * DD];// hs·Wqk [8192,1024]
__device__ __align__(256) float g_pkv [(size_t)NPOS * 4 * DD];// p-weighted kv [8192,1024]
__device__ __align__(256) float g_o   [(size_t)NPOS * DD];    // attn out [8192,256]
__device__ __align__(256) float g_x   [(size_t)NPOS * DD];    // post-LN1
__device__ __align__(256) float g_h1  [(size_t)NPOS * MLPH];  // mlp hidden
__device__ __align__(256) float g_y   [(size_t)NPOS * DD];    // pre-LN2

// ---------------- helpers ----------------
__device__ __forceinline__ float blk_sum256(float v, float* red) {
    int t = threadIdx.x;
    red[t] = v; __syncthreads();
    #pragma unroll
    for (int o = 128; o > 0; o >>= 1) {
        if (t < o) red[t] += red[t + o];
        __syncthreads();
    }
    float r = red[0]; __syncthreads();
    return r;
}

__device__ __forceinline__ float gelu_tanh(float x) {
    const float c = 0.7978845608028654f;
    float t = tanhf(c * (x + 0.044715f * x * x * x));
    return 0.5f * x * (1.f + t);
}

__device__ __forceinline__ unsigned f2tf32(float v) {
    unsigned u;
    asm("cvt.rna.tf32.f32 %0, %1;" : "=r"(u) : "f"(v));
    return u;
}

__device__ __forceinline__ void mma_tf32(float c[4], const unsigned a[4],
                                         const unsigned b[2]) {
    asm volatile(
        "mma.sync.aligned.m16n8k8.row.col.f32.tf32.tf32.f32 "
        "{%0,%1,%2,%3}, {%4,%5,%6,%7}, {%8,%9}, {%0,%1,%2,%3};\n"
        : "+f"(c[0]), "+f"(c[1]), "+f"(c[2]), "+f"(c[3])
        : "r"(a[0]), "r"(a[1]), "r"(a[2]), "r"(a[3]), "r"(b[0]), "r"(b[1]));
}

// ============================================================
// K_fold_qk (grid 260):
//  blocks 0..255 : Wqk[dd][a*256+d] = sum_e Wq[dd,a*64+e]*Wk[d*256+a*64+e]
//  blocks 256..259: bqk[a*256+d]    = sum_e bq[a*64+e]  *Wk[d*256+a*64+e]
// ============================================================
__global__ __launch_bounds__(256)
void k_fold_qk(const float* __restrict__ Wq, const float* __restrict__ Wk,
               const float* __restrict__ bq) {
    __shared__ float sA[256];
    int t = threadIdx.x, b = blockIdx.x;
    if (b < 256) {
        sA[t] = Wq[b * 256 + t];
        __syncthreads();
        #pragma unroll
        for (int a = 0; a < 4; ++a) {
            const float* wk = &Wk[t * 256 + a * 64];
            const float* wq = &sA[a * 64];
            float acc = 0.f;
            #pragma unroll 16
            for (int e = 0; e < 64; ++e) acc += wq[e] * wk[e];
            g_Wqk[b * 1024 + a * 256 + t] = acc;
        }
    } else {
        int a = b - 256;
        const float* wk = &Wk[t * 256 + a * 64];
        const float* bqp = &bq[a * 64];
        float acc = 0.f;
        #pragma unroll 16
        for (int e = 0; e < 64; ++e) acc += bqp[e] * wk[e];
        g_bqk[a * 256 + t] = acc;
    }
}

// ============================================================
// K_fold_vo (grid 1025):
//  blocks 0..1023 (a,dd): Wvo[a*256+dd][d] = sum_e Wv[dd,a*64+e]*Wo[(a*64+e)*256+d]
//  block 1024          : bvo[d] = bo[d] + sum_ae bv[ae]*Wo[ae*256+d]
// ============================================================
__global__ __launch_bounds__(256)
void k_fold_vo(const float* __restrict__ Wv, const float* __restrict__ Wo,
               const float* __restrict__ bv, const float* __restrict__ bo) {
    int t = threadIdx.x, b = blockIdx.x;
    if (b < 1024) {
        int a = b >> 8, dd = b & 255;
        const float* wo = &Wo[(a * 64) * 256 + t];
        const float* wv = &Wv[dd * 256 + a * 64];
        float acc = 0.f;
        #pragma unroll 16
        for (int e = 0; e < 64; ++e) acc += wv[e] * wo[e * 256];
        g_Wvo[(a * 256 + dd) * 256 + t] = acc;
    } else {
        float acc = bo[t];
        #pragma unroll 8
        for (int ae = 0; ae < 256; ++ae) acc += bv[ae] * Wo[ae * 256 + t];
        g_bvo[t] = acc;
    }
}

// ============================================================
// K_off: offsets = 60*sigmoid(hs@Woff + boff) - 30  -> g_off [8192,32]
// ============================================================
__global__ __launch_bounds__(256)
void k_off(const float* __restrict__ hs, const float* __restrict__ Woff,
           const float* __restrict__ boff) {
    int w = threadIdx.x >> 5, j = threadIdx.x & 31;
    int p = blockIdx.x * 8 + w;
    float hreg[8];
    #pragma unroll
    for (int i = 0; i < 8; ++i) hreg[i] = hs[(size_t)p * 256 + i * 32 + j];
    float acc = 0.f;
    #pragma unroll
    for (int i = 0; i < 8; ++i)
        #pragma unroll
        for (int l = 0; l < 32; ++l) {
            float h = __shfl_sync(0xffffffffu, hreg[i], l);
            acc += h * Woff[(i * 32 + l) * 32 + j];
        }
    float sg = 1.f / (1.f + expf(-(acc + boff[j])));
    g_off[(size_t)p * 32 + j] = 60.f * sg - 30.f;
}

// ============================================================
// K_sample_core: bilinear gather (kv in SMEM only) + scores + softmax + pkv
// 4 positions per block, 256 threads (R12-proven structure)
// ============================================================
__global__ __launch_bounds__(256)
void k_sample_core(const float* __restrict__ emb, const float* __restrict__ Wkvp,
                   const float* __restrict__ bkvp) {
    __shared__ float s_kv[16 * 258];
    __shared__ float s_qk[1024];
    __shared__ float s_off[32];
    __shared__ float s_w[SS][4];
    __shared__ int   s_idx[SS][4];
    __shared__ float s_sc[64];
    __shared__ float s_p[64];
    int t = threadIdx.x;
    float wkvp0 = Wkvp[t];
    float wkvp1 = Wkvp[DD + t];
    float bkv   = bkvp[t];

    for (int pp = 0; pp < 4; ++pp) {
        size_t p = (size_t)blockIdx.x * 4 + pp;
        int n  = (int)(p >> 12);
        int iy = ((int)p >> 6) & 63, jx = (int)p & 63;

        if (t < 32) s_off[t] = g_off[p * 32 + t];
        #pragma unroll
        for (int i = 0; i < 4; ++i)
            s_qk[i * 256 + t] = g_qk[p * 1024 + i * 256 + t];
        __syncthreads();

        if (t < SS) {
            int s = t;
            float y = fminf(fmaxf((float)iy + s_off[2*s    ], 0.f), 63.f);
            float x = fminf(fmaxf((float)jx + s_off[2*s + 1], 0.f), 63.f);
            float y0f = floorf(y), x0f = floorf(x);
            int y0 = (int)y0f, x0 = (int)x0f;
            int y1 = min(y0 + 1, 63), x1 = min(x0 + 1, 63);
            float wy = y - y0f, wx = x - x0f;
            s_w[s][0] = (1.f - wy) * (1.f - wx);
            s_w[s][1] = (1.f - wy) * wx;
            s_w[s][2] = wy * (1.f - wx);
            s_w[s][3] = wy * wx;
            int base = n * 4096;
            s_idx[s][0] = (base + y0 * 64 + x0) * DD;
            s_idx[s][1] = (base + y0 * 64 + x1) * DD;
            s_idx[s][2] = (base + y1 * 64 + x0) * DD;
            s_idx[s][3] = (base + y1 * 64 + x1) * DD;
        }
        __syncthreads();

        // gather kv + offset embedding -> SMEM only
        #pragma unroll 4
        for (int s = 0; s < SS; ++s) {
            float v = s_w[s][0] * emb[s_idx[s][0] + t]
                    + s_w[s][1] * emb[s_idx[s][1] + t]
                    + s_w[s][2] * emb[s_idx[s][2] + t]
                    + s_w[s][3] * emb[s_idx[s][3] + t];
            v += s_off[2*s] * wkvp0 + s_off[2*s + 1] * wkvp1 + bkv;
            s_kv[s * 258 + t] = v;
        }
        __syncthreads();

        // scores: 64 (a,s) pairs, 4 lanes per pair, interleaved d = sub + 4*i
        {
            int pair = t >> 2, sub = t & 3;
            int a = pair >> 4, s = pair & 15;
            const float* kvp = &s_kv[s * 258 + sub];
            const float* qkp = &s_qk[a * 256 + sub];
            float acc = 0.f;
            #pragma unroll 16
            for (int i = 0; i < 64; ++i) acc += qkp[i * 4] * kvp[i * 4];
            acc += __shfl_xor_sync(0xffffffffu, acc, 1);
            acc += __shfl_xor_sync(0xffffffffu, acc, 2);
            if (sub == 0) s_sc[pair] = acc * 0.125f;
        }
        __syncthreads();

        if (t < 4) {
            float mx = -1e30f;
            #pragma unroll
            for (int s = 0; s < 16; ++s) mx = fmaxf(mx, s_sc[t * 16 + s]);
            float sum = 0.f;
            float e[16];
            #pragma unroll
            for (int s = 0; s < 16; ++s) { e[s] = expf(s_sc[t * 16 + s] - mx); sum += e[s]; }
            float inv = 1.f / sum;
            #pragma unroll
            for (int s = 0; s < 16; ++s) s_p[t * 16 + s] = e[s] * inv;
        }
        __syncthreads();

        #pragma unroll
        for (int a = 0; a < 4; ++a) {
            float acc = 0.f;
            #pragma unroll
            for (int s = 0; s < 16; ++s)
                acc += s_p[a * 16 + s] * s_kv[s * 258 + t];
            g_pkv[p * 1024 + a * 256 + t] = acc;
        }
        __syncthreads();
    }
}

// ============================================================
// TF32 tensor-core GEMM (mma.sync m16n8k8) — fragment-order smem.
// 128x64 block tile, BK=16. 256 thr = 8 warps (4x2), warp tile 32x32.
// Staging thread (wid, lane) gathers ITS OWN fragment words from global
// and writes one STS.128 / STS.64; fragment loads are LDS.128/LDS.64,
// all conflict-free by construction. Register-prefetch of next tile.
// EPI: 0 = +bias, 1 = gelu(+bias), 2 = +bias+res
// ============================================================
template<int KTOT, int EPI>
__global__ __launch_bounds__(256)
void gemm_tf32(const float* __restrict__ A, const float* __restrict__ B,
               float* __restrict__ C, int N,
               const float* __restrict__ bias, const float* __restrict__ res) {
    __shared__ unsigned sA[2][8][32][4];   // [kc][mtile][lane][a0..a3]  8KB
    __shared__ unsigned sB[2][8][32][2];   // [kc][ntile][lane][b0..b1]  4KB
    int t = threadIdx.x, lane = t & 31, wid = t >> 5;
    int wm = wid >> 1, wn = wid & 1;           // 4 x 2 warp grid
    long rowBase = (long)blockIdx.x * 128;
    int  colBase = blockIdx.y * 64;
    int r = lane >> 2, kq = lane & 3;          // fragment row/col ids
    float c[2][4][4] = {};

    // staging bases: this thread owns fragment (kc, mt=wid, lane) of A
    // and (kc, nt=wid, lane) of B for every k-tile.
    const float* Abase = A + (rowBase + wid * 16 + r) * (long)KTOT + kq;
    const long  arow8  = 8L * KTOT;            // +8 rows
    const float* Bbase = B + (long)kq * N + colBase + wid * 8 + r;
    const long  brow4  = 4L * N;               // +4 k-rows

    // prefetch tile 0
    float pa[2][4], pb[2][2];
    #pragma unroll
    for (int kc = 0; kc < 2; ++kc) {
        const float* ap = Abase + kc * 8;
        pa[kc][0] = ap[0];      pa[kc][1] = ap[arow8];
        pa[kc][2] = ap[4];      pa[kc][3] = ap[arow8 + 4];
        const float* bp = Bbase + kc * 8L * N;
        pb[kc][0] = bp[0];      pb[kc][1] = bp[brow4];
    }

    #pragma unroll 1
    for (int k0 = 0; k0 < KTOT; k0 += 16) {
        // ---- store staged fragments (vector STS, conflict-free) ----
        #pragma unroll
        for (int kc = 0; kc < 2; ++kc) {
            uint4 av;
            av.x = f2tf32(pa[kc][0]); av.y = f2tf32(pa[kc][1]);
            av.z = f2tf32(pa[kc][2]); av.w = f2tf32(pa[kc][3]);
            *(uint4*)&sA[kc][wid][lane][0] = av;
            uint2 bv;
            bv.x = f2tf32(pb[kc][0]); bv.y = f2tf32(pb[kc][1]);
            *(uint2*)&sB[kc][wid][lane][0] = bv;
        }
        __syncthreads();

        // ---- prefetch next tile into registers (overlaps with MMA) ----
        if (k0 + 16 < KTOT) {
            #pragma unroll
            for (int kc = 0; kc < 2; ++kc) {
                const float* ap = Abase + (k0 + 16) + kc * 8;
                pa[kc][0] = ap[0];      pa[kc][1] = ap[arow8];
                pa[kc][2] = ap[4];      pa[kc][3] = ap[arow8 + 4];
                const float* bp = Bbase + (long)(k0 + 16 + kc * 8) * N;
                pb[kc][0] = bp[0];      pb[kc][1] = bp[brow4];
            }
        }

        // ---- compute: vector fragment loads + MMA ----
        #pragma unroll
        for (int kc = 0; kc < 2; ++kc) {
            unsigned af[2][4], bf[4][2];
            #pragma unroll
            for (int i = 0; i < 2; ++i)
                *(uint4*)af[i] = *(const uint4*)&sA[kc][wm * 2 + i][lane][0];
            #pragma unroll
            for (int j = 0; j < 4; ++j)
                *(uint2*)bf[j] = *(const uint2*)&sB[kc][wn * 4 + j][lane][0];
            #pragma unroll
            for (int i = 0; i < 2; ++i)
                #pragma unroll
                for (int j = 0; j < 4; ++j)
                    mma_tf32(c[i][j], af[i], bf[j]);
        }
        __syncthreads();
    }

    // ---- epilogue: c[i][j][e] -> C[row][col] ----
    #pragma unroll
    for (int i = 0; i < 2; ++i) {
        #pragma unroll
        for (int j = 0; j < 4; ++j) {
            long row0 = rowBase + wm * 32 + i * 16 + r;
            int  col0 = colBase + wn * 32 + j * 8 + 2 * kq;
            #pragma unroll
            for (int e = 0; e < 4; ++e) {
                long row = row0 + (e >> 1) * 8;
                int  col = col0 + (e & 1);
                float v = c[i][j][e] + bias[col];
                if (EPI == 1) v = gelu_tanh(v);
                if (EPI == 2) v += res[row * N + col];
                C[row * N + col] = v;
            }
        }
    }
}

// ============================================================
// K_ln: out = LN(xin (+ addin)) * sc + bi
// ============================================================
__global__ __launch_bounds__(256)
void k_ln(const float* __restrict__ xin, const float* __restrict__ addin,
          const float* __restrict__ sc, const float* __restrict__ bi,
          float* __restrict__ out) {
    __shared__ float red[256];
    int t = threadIdx.x;
    for (int pp = 0; pp < 4; ++pp) {
        size_t p = (size_t)blockIdx.x * 4 + pp;
        float x = xin[p * 256 + t];
        if (addin) x += addin[p * 256 + t];
        float sum  = blk_sum256(x, red);
        float sum2 = blk_sum256(x * x, red);
        float mean = sum * (1.f / 256.f);
        float var  = sum2 * (1.f / 256.f) - mean * mean;
        out[p * 256 + t] = (x - mean) * rsqrtf(var + 1e-6f) * sc[t] + bi[t];
    }
}

// ============================================================
extern "C" void kernel_launch(void* const* d_in, const int* in_sizes, int n_in,
                              void* d_out, int out_size) {
    const float* hs    = (const float*)d_in[0];
    const float* emb   = (const float*)d_in[1];
    const float* Woff  = (const float*)d_in[2];
    const float* boff  = (const float*)d_in[3];
    const float* Wkvp  = (const float*)d_in[4];
    const float* bkvp  = (const float*)d_in[5];
    const float* Wq    = (const float*)d_in[6];
    const float* bq    = (const float*)d_in[7];
    const float* Wk    = (const float*)d_in[8];
    const float* bk    = (const float*)d_in[9];   (void)bk; // softmax-invariant, folded out
    const float* Wv    = (const float*)d_in[10];
    const float* bv    = (const float*)d_in[11];
    const float* Wo    = (const float*)d_in[12];
    const float* bo    = (const float*)d_in[13];
    const float* ln1s  = (const float*)d_in[14];
    const float* ln1b  = (const float*)d_in[15];
    const float* ln2s  = (const float*)d_in[16];
    const float* ln2b  = (const float*)d_in[17];
    const float* W1    = (const float*)d_in[18];
    const float* b1    = (const float*)d_in[19];
    const float* W2    = (const float*)d_in[20];
    const float* b2    = (const float*)d_in[21];
    float* out = (float*)d_out;

    float *p_Wqk, *p_Wvo, *p_bqk, *p_bvo;
    float *p_qk, *p_pkv, *p_o, *p_x, *p_h1, *p_y;
    cudaGetSymbolAddress((void**)&p_Wqk,  g_Wqk);
    cudaGetSymbolAddress((void**)&p_Wvo,  g_Wvo);
    cudaGetSymbolAddress((void**)&p_bqk,  g_bqk);
    cudaGetSymbolAddress((void**)&p_bvo,  g_bvo);
    cudaGetSymbolAddress((void**)&p_qk,   g_qk);
    cudaGetSymbolAddress((void**)&p_pkv,  g_pkv);
    cudaGetSymbolAddress((void**)&p_o,    g_o);
    cudaGetSymbolAddress((void**)&p_x,    g_x);
    cudaGetSymbolAddress((void**)&p_h1,   g_h1);
    cudaGetSymbolAddress((void**)&p_y,    g_y);

    // ---- one-time weight folding (2 wide parallel kernels) ----
    k_fold_qk<<<260, 256>>>(Wq, Wk, bq);
    k_fold_vo<<<1025, 256>>>(Wv, Wo, bv, bo);

    // ---- main pipeline ----
    k_off<<<NPOS / 8, 256>>>(hs, Woff, boff);
    // qk = hs @ Wqk + bqk   [tf32]
    gemm_tf32<256, 0><<<dim3(64, 16), 256>>>(hs, p_Wqk, p_qk, 1024, p_bqk, nullptr);
    // fused: gather kv (SMEM) + scores + softmax + pkv  (4 pos/block)
    k_sample_core<<<NPOS / 4, 256>>>(emb, Wkvp, bkvp);
    // o = pkv @ Wvo + bvo   [tf32]
    gemm_tf32<1024, 0><<<dim3(64, 4), 256>>>(p_pkv, p_Wvo, p_o, 256, p_bvo, nullptr);
    // x = LN1(hs + o)
    k_ln<<<NPOS / 4, 256>>>(hs, p_o, ln1s, ln1b, p_x);
    // h1 = gelu(x @ W1 + b1)   [tf32]
    gemm_tf32<256, 1><<<dim3(64, 16), 256>>>(p_x, W1, p_h1, 1024, b1, nullptr);
    // y = x + h1 @ W2 + b2     [tf32]
    gemm_tf32<1024, 2><<<dim3(64, 4), 256>>>(p_h1, W2, p_y, 256, b2, p_x);
    // out = LN2(y)
    k_ln<<<NPOS / 4, 256>>>(p_y, nullptr, ln2s, ln2b, out);
}

// round 16
// speedup vs baseline: 1.2258x; 1.2258x over previous
#include <cuda_runtime.h>
#include <cuda_bf16.h>
#include <math.h>

// ---------------- problem dims ----------------
#define NB 2
#define HH 64
#define WW 64
#define DD 256
#define SS 16
#define NHD 4
#define HDIM 64
#define MLPH 1024
#define NPOS (NB*HH*WW)          // 8192
#define NKV  (NPOS*SS)           // 131072

// ---------------- scratch (device globals; no allocations allowed) -------
__device__ __align__(256) float g_off [(size_t)NPOS * 32];    // transformed offsets
__device__ __align__(256) float g_Wqk [DD * 4 * DD];          // folded Wq·Wk^T [256,1024]
__device__ __align__(256) float g_Wvo [4 * DD * DD];          // folded Wv·Wo   [1024,256]
__device__ __align__(256) float g_bqk [4 * DD];               // folded bq·Wk^T [1024]
__device__ __align__(256) float g_bvo [DD];                   // folded bo+bv·Wo [256]
__device__ __align__(256) float g_qk  [(size_t)NPOS * 4 * DD];// hs·Wqk [8192,1024]
__device__ __align__(256) float g_pkv [(size_t)NPOS * 4 * DD];// p-weighted kv [8192,1024]
__device__ __align__(256) float g_o   [(size_t)NPOS * DD];    // attn out [8192,256]
__device__ __align__(256) float g_x   [(size_t)NPOS * DD];    // post-LN1
__device__ __align__(256) float g_h1  [(size_t)NPOS * MLPH];  // mlp hidden
__device__ __align__(256) float g_y   [(size_t)NPOS * DD];    // pre-LN2

// ---------------- helpers ----------------
__device__ __forceinline__ float blk_sum256(float v, float* red) {
    int t = threadIdx.x;
    red[t] = v; __syncthreads();
    #pragma unroll
    for (int o = 128; o > 0; o >>= 1) {
        if (t < o) red[t] += red[t + o];
        __syncthreads();
    }
    float r = red[0]; __syncthreads();
    return r;
}

__device__ __forceinline__ float gelu_tanh(float x) {
    const float c = 0.7978845608028654f;
    float t = tanhf(c * (x + 0.044715f * x * x * x));
    return 0.5f * x * (1.f + t);
}

__device__ __forceinline__ unsigned f2tf32(float v) {
    unsigned u;
    asm("cvt.rna.tf32.f32 %0, %1;" : "=r"(u) : "f"(v));
    return u;
}

__device__ __forceinline__ void mma_tf32(float c[4], const unsigned a[4],
                                         const unsigned b[2]) {
    asm volatile(
        "mma.sync.aligned.m16n8k8.row.col.f32.tf32.tf32.f32 "
        "{%0,%1,%2,%3}, {%4,%5,%6,%7}, {%8,%9}, {%0,%1,%2,%3};\n"
        : "+f"(c[0]), "+f"(c[1]), "+f"(c[2]), "+f"(c[3])
        : "r"(a[0]), "r"(a[1]), "r"(a[2]), "r"(a[3]), "r"(b[0]), "r"(b[1]));
}

__device__ __forceinline__ void cp_async16(void* smem_dst, const void* gsrc) {
    unsigned s = (unsigned)__cvta_generic_to_shared(smem_dst);
    asm volatile("cp.async.ca.shared.global [%0], [%1], 16;\n" :: "r"(s), "l"(gsrc));
}

// ============================================================
// K_fold_qk (grid 260):
//  blocks 0..255 : Wqk[dd][a*256+d] = sum_e Wq[dd,a*64+e]*Wk[d*256+a*64+e]
//  blocks 256..259: bqk[a*256+d]    = sum_e bq[a*64+e]  *Wk[d*256+a*64+e]
// ============================================================
__global__ __launch_bounds__(256)
void k_fold_qk(const float* __restrict__ Wq, const float* __restrict__ Wk,
               const float* __restrict__ bq) {
    __shared__ float sA[256];
    int t = threadIdx.x, b = blockIdx.x;
    if (b < 256) {
        sA[t] = Wq[b * 256 + t];
        __syncthreads();
        #pragma unroll
        for (int a = 0; a < 4; ++a) {
            const float* wk = &Wk[t * 256 + a * 64];
            const float* wq = &sA[a * 64];
            float acc = 0.f;
            #pragma unroll 16
            for (int e = 0; e < 64; ++e) acc += wq[e] * wk[e];
            g_Wqk[b * 1024 + a * 256 + t] = acc;
        }
    } else {
        int a = b - 256;
        const float* wk = &Wk[t * 256 + a * 64];
        const float* bqp = &bq[a * 64];
        float acc = 0.f;
        #pragma unroll 16
        for (int e = 0; e < 64; ++e) acc += bqp[e] * wk[e];
        g_bqk[a * 256 + t] = acc;
    }
}

// ============================================================
// K_fold_vo (grid 1025):
//  blocks 0..1023 (a,dd): Wvo[a*256+dd][d] = sum_e Wv[dd,a*64+e]*Wo[(a*64+e)*256+d]
//  block 1024          : bvo[d] = bo[d] + sum_ae bv[ae]*Wo[ae*256+d]
// ============================================================
__global__ __launch_bounds__(256)
void k_fold_vo(const float* __restrict__ Wv, const float* __restrict__ Wo,
               const float* __restrict__ bv, const float* __restrict__ bo) {
    int t = threadIdx.x, b = blockIdx.x;
    if (b < 1024) {
        int a = b >> 8, dd = b & 255;
        const float* wo = &Wo[(a * 64) * 256 + t];
        const float* wv = &Wv[dd * 256 + a * 64];
        float acc = 0.f;
        #pragma unroll 16
        for (int e = 0; e < 64; ++e) acc += wv[e] * wo[e * 256];
        g_Wvo[(a * 256 + dd) * 256 + t] = acc;
    } else {
        float acc = bo[t];
        #pragma unroll 8
        for (int ae = 0; ae < 256; ++ae) acc += bv[ae] * Wo[ae * 256 + t];
        g_bvo[t] = acc;
    }
}

// ============================================================
// K_off: offsets = 60*sigmoid(hs@Woff + boff) - 30  -> g_off [8192,32]
// ============================================================
__global__ __launch_bounds__(256)
void k_off(const float* __restrict__ hs, const float* __restrict__ Woff,
           const float* __restrict__ boff) {
    int w = threadIdx.x >> 5, j = threadIdx.x & 31;
    int p = blockIdx.x * 8 + w;
    float hreg[8];
    #pragma unroll
    for (int i = 0; i < 8; ++i) hreg[i] = hs[(size_t)p * 256 + i * 32 + j];
    float acc = 0.f;
    #pragma unroll
    for (int i = 0; i < 8; ++i)
        #pragma unroll
        for (int l = 0; l < 32; ++l) {
            float h = __shfl_sync(0xffffffffu, hreg[i], l);
            acc += h * Woff[(i * 32 + l) * 32 + j];
        }
    float sg = 1.f / (1.f + expf(-(acc + boff[j])));
    g_off[(size_t)p * 32 + j] = 60.f * sg - 30.f;
}

// ============================================================
// K_sample_core: bilinear gather (kv in SMEM only) + scores + softmax + pkv
// 4 positions per block, 256 threads (R12-proven structure)
// ============================================================
__global__ __launch_bounds__(256)
void k_sample_core(const float* __restrict__ emb, const float* __restrict__ Wkvp,
                   const float* __restrict__ bkvp) {
    __shared__ float s_kv[16 * 258];
    __shared__ float s_qk[1024];
    __shared__ float s_off[32];
    __shared__ float s_w[SS][4];
    __shared__ int   s_idx[SS][4];
    __shared__ float s_sc[64];
    __shared__ float s_p[64];
    int t = threadIdx.x;
    float wkvp0 = Wkvp[t];
    float wkvp1 = Wkvp[DD + t];
    float bkv   = bkvp[t];

    for (int pp = 0; pp < 4; ++pp) {
        size_t p = (size_t)blockIdx.x * 4 + pp;
        int n  = (int)(p >> 12);
        int iy = ((int)p >> 6) & 63, jx = (int)p & 63;

        if (t < 32) s_off[t] = g_off[p * 32 + t];
        #pragma unroll
        for (int i = 0; i < 4; ++i)
            s_qk[i * 256 + t] = g_qk[p * 1024 + i * 256 + t];
        __syncthreads();

        if (t < SS) {
            int s = t;
            float y = fminf(fmaxf((float)iy + s_off[2*s    ], 0.f), 63.f);
            float x = fminf(fmaxf((float)jx + s_off[2*s + 1], 0.f), 63.f);
            float y0f = floorf(y), x0f = floorf(x);
            int y0 = (int)y0f, x0 = (int)x0f;
            int y1 = min(y0 + 1, 63), x1 = min(x0 + 1, 63);
            float wy = y - y0f, wx = x - x0f;
            s_w[s][0] = (1.f - wy) * (1.f - wx);
            s_w[s][1] = (1.f - wy) * wx;
            s_w[s][2] = wy * (1.f - wx);
            s_w[s][3] = wy * wx;
            int base = n * 4096;
            s_idx[s][0] = (base + y0 * 64 + x0) * DD;
            s_idx[s][1] = (base + y0 * 64 + x1) * DD;
            s_idx[s][2] = (base + y1 * 64 + x0) * DD;
            s_idx[s][3] = (base + y1 * 64 + x1) * DD;
        }
        __syncthreads();

        // gather kv + offset embedding -> SMEM only
        #pragma unroll 4
        for (int s = 0; s < SS; ++s) {
            float v = s_w[s][0] * emb[s_idx[s][0] + t]
                    + s_w[s][1] * emb[s_idx[s][1] + t]
                    + s_w[s][2] * emb[s_idx[s][2] + t]
                    + s_w[s][3] * emb[s_idx[s][3] + t];
            v += s_off[2*s] * wkvp0 + s_off[2*s + 1] * wkvp1 + bkv;
            s_kv[s * 258 + t] = v;
        }
        __syncthreads();

        // scores: 64 (a,s) pairs, 4 lanes per pair, interleaved d = sub + 4*i
        {
            int pair = t >> 2, sub = t & 3;
            int a = pair >> 4, s = pair & 15;
            const float* kvp = &s_kv[s * 258 + sub];
            const float* qkp = &s_qk[a * 256 + sub];
            float acc = 0.f;
            #pragma unroll 16
            for (int i = 0; i < 64; ++i) acc += qkp[i * 4] * kvp[i * 4];
            acc += __shfl_xor_sync(0xffffffffu, acc, 1);
            acc += __shfl_xor_sync(0xffffffffu, acc, 2);
            if (sub == 0) s_sc[pair] = acc * 0.125f;
        }
        __syncthreads();

        if (t < 4) {
            float mx = -1e30f;
            #pragma unroll
            for (int s = 0; s < 16; ++s) mx = fmaxf(mx, s_sc[t * 16 + s]);
            float sum = 0.f;
            float e[16];
            #pragma unroll
            for (int s = 0; s < 16; ++s) { e[s] = expf(s_sc[t * 16 + s] - mx); sum += e[s]; }
            float inv = 1.f / sum;
            #pragma unroll
            for (int s = 0; s < 16; ++s) s_p[t * 16 + s] = e[s] * inv;
        }
        __syncthreads();

        #pragma unroll
        for (int a = 0; a < 4; ++a) {
            float acc = 0.f;
            #pragma unroll
            for (int s = 0; s < 16; ++s)
                acc += s_p[a * 16 + s] * s_kv[s * 258 + t];
            g_pkv[p * 1024 + a * 256 + t] = acc;
        }
        __syncthreads();
    }
}

// ============================================================
// TF32 tensor-core GEMM (mma.sync m16n8k8) — cp.async double-buffered.
// 128x64 block tile, BK=16. 256 thr = 8 warps (4x2), warp tile 32x32.
// A smem row-major [128][20] (stride 20 -> fragment LDS conflict-free),
// B smem [16][68]. cvt to tf32 at fragment load (R12 numerics).
// EPI: 0 = +bias, 1 = gelu(+bias), 2 = +bias+res
// ============================================================
template<int KTOT, int EPI>
__global__ __launch_bounds__(256)
void gemm_tf32(const float* __restrict__ A, const float* __restrict__ B,
               float* __restrict__ C, int N,
               const float* __restrict__ bias, const float* __restrict__ res) {
    __shared__ float As[2][128][20];
    __shared__ float Bs[2][16][68];
    int t = threadIdx.x, lane = t & 31, wid = t >> 5;
    int wm = wid >> 1, wn = wid & 1;           // 4 x 2 warp grid
    long rowBase = (long)blockIdx.x * 128;
    int  colBase = blockIdx.y * 64;
    int r = lane >> 2, kq = lane & 3;          // fragment row/col within warp
    float c[2][4][4] = {};

    // staging indices (cp.async, fully coalesced 16B)
    int am = t >> 2, ac = (t & 3) * 4;          // A: rows am, am+64; cols ac..ac+3
    int bk = t >> 4, bn = (t & 15) * 4;         // B: row bk, cols bn..bn+3

    // prologue: stage tile 0 into buffer 0
    {
        const float* a0 = &A[(rowBase + am) * (long)KTOT + ac];
        cp_async16(&As[0][am][ac], a0);
        cp_async16(&As[0][am + 64][ac], a0 + 64L * KTOT);
        cp_async16(&Bs[0][bk][bn], &B[(long)bk * N + colBase + bn]);
    }
    asm volatile("cp.async.commit_group;\n");

    #pragma unroll 1
    for (int k0 = 0; k0 < KTOT; k0 += 16) {
        int buf = (k0 >> 4) & 1;
        // stage next tile into other buffer (in flight during compute)
        if (k0 + 16 < KTOT) {
            const float* a0 = &A[(rowBase + am) * (long)KTOT + (k0 + 16) + ac];
            cp_async16(&As[buf ^ 1][am][ac], a0);
            cp_async16(&As[buf ^ 1][am + 64][ac], a0 + 64L * KTOT);
            cp_async16(&Bs[buf ^ 1][bk][bn],
                       &B[(long)(k0 + 16 + bk) * N + colBase + bn]);
        }
        asm volatile("cp.async.commit_group;\n");
        asm volatile("cp.async.wait_group 1;\n" ::: "memory");
        __syncthreads();

        #pragma unroll
        for (int ks = 0; ks < 2; ++ks) {
            int kb = ks * 8;
            unsigned af[2][4], bf[4][2];
            #pragma unroll
            for (int i = 0; i < 2; ++i) {
                int m0 = wm * 32 + i * 16;
                af[i][0] = f2tf32(As[buf][m0 + r    ][kb + kq    ]);
                af[i][1] = f2tf32(As[buf][m0 + r + 8][kb + kq    ]);
                af[i][2] = f2tf32(As[buf][m0 + r    ][kb + kq + 4]);
                af[i][3] = f2tf32(As[buf][m0 + r + 8][kb + kq + 4]);
            }
            #pragma unroll
            for (int j = 0; j < 4; ++j) {
                int n0 = wn * 32 + j * 8;
                bf[j][0] = f2tf32(Bs[buf][kb + kq    ][n0 + r]);
                bf[j][1] = f2tf32(Bs[buf][kb + kq + 4][n0 + r]);
            }
            #pragma unroll
            for (int i = 0; i < 2; ++i)
                #pragma unroll
                for (int j = 0; j < 4; ++j)
                    mma_tf32(c[i][j], af[i], bf[j]);
        }
        __syncthreads();
    }

    // ---- epilogue: c[i][j][e] -> C[row][col] ----
    #pragma unroll
    for (int i = 0; i < 2; ++i) {
        #pragma unroll
        for (int j = 0; j < 4; ++j) {
            long row0 = rowBase + wm * 32 + i * 16 + r;
            int  col0 = colBase + wn * 32 + j * 8 + 2 * kq;
            #pragma unroll
            for (int e = 0; e < 4; ++e) {
                long row = row0 + (e >> 1) * 8;
                int  col = col0 + (e & 1);
                float v = c[i][j][e] + bias[col];
                if (EPI == 1) v = gelu_tanh(v);
                if (EPI == 2) v += res[row * N + col];
                C[row * N + col] = v;
            }
        }
    }
}

// ============================================================
// K_ln: out = LN(xin (+ addin)) * sc + bi
// ============================================================
__global__ __launch_bounds__(256)
void k_ln(const float* __restrict__ xin, const float* __restrict__ addin,
          const float* __restrict__ sc, const float* __restrict__ bi,
          float* __restrict__ out) {
    __shared__ float red[256];
    int t = threadIdx.x;
    for (int pp = 0; pp < 4; ++pp) {
        size_t p = (size_t)blockIdx.x * 4 + pp;
        float x = xin[p * 256 + t];
        if (addin) x += addin[p * 256 + t];
        float sum  = blk_sum256(x, red);
        float sum2 = blk_sum256(x * x, red);
        float mean = sum * (1.f / 256.f);
        float var  = sum2 * (1.f / 256.f) - mean * mean;
        out[p * 256 + t] = (x - mean) * rsqrtf(var + 1e-6f) * sc[t] + bi[t];
    }
}

// ============================================================
extern "C" void kernel_launch(void* const* d_in, const int* in_sizes, int n_in,
                              void* d_out, int out_size) {
    const float* hs    = (const float*)d_in[0];
    const float* emb   = (const float*)d_in[1];
    const float* Woff  = (const float*)d_in[2];
    const float* boff  = (const float*)d_in[3];
    const float* Wkvp  = (const float*)d_in[4];
    const float* bkvp  = (const float*)d_in[5];
    const float* Wq    = (const float*)d_in[6];
    const float* bq    = (const float*)d_in[7];
    const float* Wk    = (const float*)d_in[8];
    const float* bk    = (const float*)d_in[9];   (void)bk; // softmax-invariant, folded out
    const float* Wv    = (const float*)d_in[10];
    const float* bv    = (const float*)d_in[11];
    const float* Wo    = (const float*)d_in[12];
    const float* bo    = (const float*)d_in[13];
    const float* ln1s  = (const float*)d_in[14];
    const float* ln1b  = (const float*)d_in[15];
    const float* ln2s  = (const float*)d_in[16];
    const float* ln2b  = (const float*)d_in[17];
    const float* W1    = (const float*)d_in[18];
    const float* b1    = (const float*)d_in[19];
    const float* W2    = (const float*)d_in[20];
    const float* b2    = (const float*)d_in[21];
    float* out = (float*)d_out;

    float *p_Wqk, *p_Wvo, *p_bqk, *p_bvo;
    float *p_qk, *p_pkv, *p_o, *p_x, *p_h1, *p_y;
    cudaGetSymbolAddress((void**)&p_Wqk,  g_Wqk);
    cudaGetSymbolAddress((void**)&p_Wvo,  g_Wvo);
    cudaGetSymbolAddress((void**)&p_bqk,  g_bqk);
    cudaGetSymbolAddress((void**)&p_bvo,  g_bvo);
    cudaGetSymbolAddress((void**)&p_qk,   g_qk);
    cudaGetSymbolAddress((void**)&p_pkv,  g_pkv);
    cudaGetSymbolAddress((void**)&p_o,    g_o);
    cudaGetSymbolAddress((void**)&p_x,    g_x);
    cudaGetSymbolAddress((void**)&p_h1,   g_h1);
    cudaGetSymbolAddress((void**)&p_y,    g_y);

    // ---- one-time weight folding (2 wide parallel kernels) ----
    k_fold_qk<<<260, 256>>>(Wq, Wk, bq);
    k_fold_vo<<<1025, 256>>>(Wv, Wo, bv, bo);

    // ---- main pipeline ----
    k_off<<<NPOS / 8, 256>>>(hs, Woff, boff);
    // qk = hs @ Wqk + bqk   [tf32]
    gemm_tf32<256, 0><<<dim3(64, 16), 256>>>(hs, p_Wqk, p_qk, 1024, p_bqk, nullptr);
    // fused: gather kv (SMEM) + scores + softmax + pkv  (4 pos/block)
    k_sample_core<<<NPOS / 4, 256>>>(emb, Wkvp, bkvp);
    // o = pkv @ Wvo + bvo   [tf32]
    gemm_tf32<1024, 0><<<dim3(64, 4), 256>>>(p_pkv, p_Wvo, p_o, 256, p_bvo, nullptr);
    // x = LN1(hs + o)
    k_ln<<<NPOS / 4, 256>>>(hs, p_o, ln1s, ln1b, p_x);
    // h1 = gelu(x @ W1 + b1)   [tf32]
    gemm_tf32<256, 1><<<dim3(64, 16), 256>>>(p_x, W1, p_h1, 1024, b1, nullptr);
    // y = x + h1 @ W2 + b2     [tf32]
    gemm_tf32<1024, 2><<<dim3(64, 4), 256>>>(p_h1, W2, p_y, 256, b2, p_x);
    // out = LN2(y)
    k_ln<<<NPOS / 4, 256>>>(p_y, nullptr, ln2s, ln2b, out);
}

// round 17
// speedup vs baseline: 1.2403x; 1.0118x over previous
#include <cuda_runtime.h>
#include <cuda_bf16.h>
#include <math.h>

// ---------------- problem dims ----------------
#define NB 2
#define HH 64
#define WW 64
#define DD 256
#define SS 16
#define NHD 4
#define HDIM 64
#define MLPH 1024
#define NPOS (NB*HH*WW)          // 8192
#define NKV  (NPOS*SS)           // 131072

// ---------------- scratch (device globals; no allocations allowed) -------
__device__ __align__(256) float g_off [(size_t)NPOS * 32];    // transformed offsets
__device__ __align__(256) float g_Wqk [DD * 4 * DD];          // folded Wq·Wk^T [256,1024] (tf32-rounded)
__device__ __align__(256) float g_Wvo [4 * DD * DD];          // folded Wv·Wo   [1024,256] (tf32-rounded)
__device__ __align__(256) float g_W1r [DD * MLPH];            // W1 tf32-rounded copy
__device__ __align__(256) float g_W2r [MLPH * DD];            // W2 tf32-rounded copy
__device__ __align__(256) float g_bqk [4 * DD];               // folded bq·Wk^T [1024]
__device__ __align__(256) float g_bvo [DD];                   // folded bo+bv·Wo [256]
__device__ __align__(256) float g_qk  [(size_t)NPOS * 4 * DD];// hs·Wqk [8192,1024]
__device__ __align__(256) float g_pkv [(size_t)NPOS * 4 * DD];// p-weighted kv (tf32-rounded)
__device__ __align__(256) float g_o   [(size_t)NPOS * DD];    // attn out [8192,256]
__device__ __align__(256) float g_x   [(size_t)NPOS * DD];    // post-LN1
__device__ __align__(256) float g_h1  [(size_t)NPOS * MLPH];  // mlp hidden (tf32-rounded)
__device__ __align__(256) float g_y   [(size_t)NPOS * DD];    // pre-LN2

// ---------------- helpers ----------------
__device__ __forceinline__ float blk_sum256(float v, float* red) {
    int t = threadIdx.x;
    red[t] = v; __syncthreads();
    #pragma unroll
    for (int o = 128; o > 0; o >>= 1) {
        if (t < o) red[t] += red[t + o];
        __syncthreads();
    }
    float r = red[0]; __syncthreads();
    return r;
}

__device__ __forceinline__ float gelu_tanh(float x) {
    const float c = 0.7978845608028654f;
    float t = tanhf(c * (x + 0.044715f * x * x * x));
    return 0.5f * x * (1.f + t);
}

__device__ __forceinline__ unsigned f2tf32(float v) {
    unsigned u;
    asm("cvt.rna.tf32.f32 %0, %1;" : "=r"(u) : "f"(v));
    return u;
}

__device__ __forceinline__ float round_tf32(float v) {
    return __uint_as_float(f2tf32(v));
}

__device__ __forceinline__ void mma_tf32(float c[4], const unsigned a[4],
                                         const unsigned b[2]) {
    asm volatile(
        "mma.sync.aligned.m16n8k8.row.col.f32.tf32.tf32.f32 "
        "{%0,%1,%2,%3}, {%4,%5,%6,%7}, {%8,%9}, {%0,%1,%2,%3};\n"
        : "+f"(c[0]), "+f"(c[1]), "+f"(c[2]), "+f"(c[3])
        : "r"(a[0]), "r"(a[1]), "r"(a[2]), "r"(a[3]), "r"(b[0]), "r"(b[1]));
}

__device__ __forceinline__ void cp_async16(void* smem_dst, const void* gsrc) {
    unsigned s = (unsigned)__cvta_generic_to_shared(smem_dst);
    asm volatile("cp.async.ca.shared.global [%0], [%1], 16;\n" :: "r"(s), "l"(gsrc));
}

// ============================================================
// K_fold_qk (grid 260): stores tf32-rounded Wqk
// ============================================================
__global__ __launch_bounds__(256)
void k_fold_qk(const float* __restrict__ Wq, const float* __restrict__ Wk,
               const float* __restrict__ bq) {
    __shared__ float sA[256];
    int t = threadIdx.x, b = blockIdx.x;
    if (b < 256) {
        sA[t] = Wq[b * 256 + t];
        __syncthreads();
        #pragma unroll
        for (int a = 0; a < 4; ++a) {
            const float* wk = &Wk[t * 256 + a * 64];
            const float* wq = &sA[a * 64];
            float acc = 0.f;
            #pragma unroll 16
            for (int e = 0; e < 64; ++e) acc += wq[e] * wk[e];
            g_Wqk[b * 1024 + a * 256 + t] = round_tf32(acc);
        }
    } else {
        int a = b - 256;
        const float* wk = &Wk[t * 256 + a * 64];
        const float* bqp = &bq[a * 64];
        float acc = 0.f;
        #pragma unroll 16
        for (int e = 0; e < 64; ++e) acc += bqp[e] * wk[e];
        g_bqk[a * 256 + t] = acc;
    }
}

// ============================================================
// K_fold_vo (grid 1025): stores tf32-rounded Wvo
// ============================================================
__global__ __launch_bounds__(256)
void k_fold_vo(const float* __restrict__ Wv, const float* __restrict__ Wo,
               const float* __restrict__ bv, const float* __restrict__ bo) {
    int t = threadIdx.x, b = blockIdx.x;
    if (b < 1024) {
        int a = b >> 8, dd = b & 255;
        const float* wo = &Wo[(a * 64) * 256 + t];
        const float* wv = &Wv[dd * 256 + a * 64];
        float acc = 0.f;
        #pragma unroll 16
        for (int e = 0; e < 64; ++e) acc += wv[e] * wo[e * 256];
        g_Wvo[(a * 256 + dd) * 256 + t] = round_tf32(acc);
    } else {
        float acc = bo[t];
        #pragma unroll 8
        for (int ae = 0; ae < 256; ++ae) acc += bv[ae] * Wo[ae * 256 + t];
        g_bvo[t] = acc;
    }
}

// ============================================================
// K_cvt_w (grid 2048): tf32-rounded copies of W1, W2
// ============================================================
__global__ __launch_bounds__(256)
void k_cvt_w(const float* __restrict__ W1, const float* __restrict__ W2) {
    int i = blockIdx.x * 256 + threadIdx.x;      // 524288 total
    if (i < DD * MLPH) g_W1r[i] = round_tf32(W1[i]);
    else               g_W2r[i - DD * MLPH] = round_tf32(W2[i - DD * MLPH]);
}

// ============================================================
// K_off: offsets = 60*sigmoid(hs@Woff + boff) - 30  -> g_off [8192,32]
// ============================================================
__global__ __launch_bounds__(256)
void k_off(const float* __restrict__ hs, const float* __restrict__ Woff,
           const float* __restrict__ boff) {
    int w = threadIdx.x >> 5, j = threadIdx.x & 31;
    int p = blockIdx.x * 8 + w;
    float hreg[8];
    #pragma unroll
    for (int i = 0; i < 8; ++i) hreg[i] = hs[(size_t)p * 256 + i * 32 + j];
    float acc = 0.f;
    #pragma unroll
    for (int i = 0; i < 8; ++i)
        #pragma unroll
        for (int l = 0; l < 32; ++l) {
            float h = __shfl_sync(0xffffffffu, hreg[i], l);
            acc += h * Woff[(i * 32 + l) * 32 + j];
        }
    float sg = 1.f / (1.f + expf(-(acc + boff[j])));
    g_off[(size_t)p * 32 + j] = 60.f * sg - 30.f;
}

// ============================================================
// K_sample_core: bilinear gather (kv in SMEM only) + scores + softmax + pkv
// 4 positions per block, 256 threads. pkv stored tf32-rounded (consumed
// only by the vo GEMM, which rounded it at load anyway -> bit-identical).
// ============================================================
__global__ __launch_bounds__(256)
void k_sample_core(const float* __restrict__ emb, const float* __restrict__ Wkvp,
                   const float* __restrict__ bkvp) {
    __shared__ float s_kv[16 * 258];
    __shared__ float s_qk[1024];
    __shared__ float s_off[32];
    __shared__ float s_w[SS][4];
    __shared__ int   s_idx[SS][4];
    __shared__ float s_sc[64];
    __shared__ float s_p[64];
    int t = threadIdx.x;
    float wkvp0 = Wkvp[t];
    float wkvp1 = Wkvp[DD + t];
    float bkv   = bkvp[t];

    for (int pp = 0; pp < 4; ++pp) {
        size_t p = (size_t)blockIdx.x * 4 + pp;
        int n  = (int)(p >> 12);
        int iy = ((int)p >> 6) & 63, jx = (int)p & 63;

        if (t < 32) s_off[t] = g_off[p * 32 + t];
        #pragma unroll
        for (int i = 0; i < 4; ++i)
            s_qk[i * 256 + t] = g_qk[p * 1024 + i * 256 + t];
        __syncthreads();

        if (t < SS) {
            int s = t;
            float y = fminf(fmaxf((float)iy + s_off[2*s    ], 0.f), 63.f);
            float x = fminf(fmaxf((float)jx + s_off[2*s + 1], 0.f), 63.f);
            float y0f = floorf(y), x0f = floorf(x);
            int y0 = (int)y0f, x0 = (int)x0f;
            int y1 = min(y0 + 1, 63), x1 = min(x0 + 1, 63);
            float wy = y - y0f, wx = x - x0f;
            s_w[s][0] = (1.f - wy) * (1.f - wx);
            s_w[s][1] = (1.f - wy) * wx;
            s_w[s][2] = wy * (1.f - wx);
            s_w[s][3] = wy * wx;
            int base = n * 4096;
            s_idx[s][0] = (base + y0 * 64 + x0) * DD;
            s_idx[s][1] = (base + y0 * 64 + x1) * DD;
            s_idx[s][2] = (base + y1 * 64 + x0) * DD;
            s_idx[s][3] = (base + y1 * 64 + x1) * DD;
        }
        __syncthreads();

        // gather kv + offset embedding -> SMEM only
        #pragma unroll 4
        for (int s = 0; s < SS; ++s) {
            float v = s_w[s][0] * emb[s_idx[s][0] + t]
                    + s_w[s][1] * emb[s_idx[s][1] + t]
                    + s_w[s][2] * emb[s_idx[s][2] + t]
                    + s_w[s][3] * emb[s_idx[s][3] + t];
            v += s_off[2*s] * wkvp0 + s_off[2*s + 1] * wkvp1 + bkv;
            s_kv[s * 258 + t] = v;
        }
        __syncthreads();

        // scores: 64 (a,s) pairs, 4 lanes per pair, interleaved d = sub + 4*i
        {
            int pair = t >> 2, sub = t & 3;
            int a = pair >> 4, s = pair & 15;
            const float* kvp = &s_kv[s * 258 + sub];
            const float* qkp = &s_qk[a * 256 + sub];
            float acc = 0.f;
            #pragma unroll 16
            for (int i = 0; i < 64; ++i) acc += qkp[i * 4] * kvp[i * 4];
            acc += __shfl_xor_sync(0xffffffffu, acc, 1);
            acc += __shfl_xor_sync(0xffffffffu, acc, 2);
            if (sub == 0) s_sc[pair] = acc * 0.125f;
        }
        __syncthreads();

        if (t < 4) {
            float mx = -1e30f;
            #pragma unroll
            for (int s = 0; s < 16; ++s) mx = fmaxf(mx, s_sc[t * 16 + s]);
            float sum = 0.f;
            float e[16];
            #pragma unroll
            for (int s = 0; s < 16; ++s) { e[s] = expf(s_sc[t * 16 + s] - mx); sum += e[s]; }
            float inv = 1.f / sum;
            #pragma unroll
            for (int s = 0; s < 16; ++s) s_p[t * 16 + s] = e[s] * inv;
        }
        __syncthreads();

        #pragma unroll
        for (int a = 0; a < 4; ++a) {
            float acc = 0.f;
            #pragma unroll
            for (int s = 0; s < 16; ++s)
                acc += s_p[a * 16 + s] * s_kv[s * 258 + t];
            g_pkv[p * 1024 + a * 256 + t] = round_tf32(acc);
        }
        __syncthreads();
    }
}

// ============================================================
// TF32 tensor-core GEMM (mma.sync m16n8k8) — cp.async double-buffered.
// 128x64 block tile, BK=16. 256 thr = 8 warps (4x2), warp tile 32x32.
// B operands are ALWAYS pre-rounded tf32 (raw reinterpret, no cvt).
// CVTA=1: cvt A at fragment load; CVTA=0: A pre-rounded too.
// EPI: 0 = +bias, 1 = gelu(+bias), rounded store, 2 = +bias+res
// ============================================================
template<int KTOT, int EPI, int CVTA>
__global__ __launch_bounds__(256)
void gemm_tf32(const float* __restrict__ A, const float* __restrict__ B,
               float* __restrict__ C, int N,
               const float* __restrict__ bias, const float* __restrict__ res) {
    __shared__ float As[2][128][20];
    __shared__ float Bs[2][16][68];
    int t = threadIdx.x, lane = t & 31, wid = t >> 5;
    int wm = wid >> 1, wn = wid & 1;           // 4 x 2 warp grid
    long rowBase = (long)blockIdx.x * 128;
    int  colBase = blockIdx.y * 64;
    int r = lane >> 2, kq = lane & 3;          // fragment row/col within warp
    float c[2][4][4] = {};

    // staging indices (cp.async, fully coalesced 16B)
    int am = t >> 2, ac = (t & 3) * 4;          // A: rows am, am+64; cols ac..ac+3
    int bk = t >> 4, bn = (t & 15) * 4;         // B: row bk, cols bn..bn+3

    // prologue: stage tile 0 into buffer 0
    {
        const float* a0 = &A[(rowBase + am) * (long)KTOT + ac];
        cp_async16(&As[0][am][ac], a0);
        cp_async16(&As[0][am + 64][ac], a0 + 64L * KTOT);
        cp_async16(&Bs[0][bk][bn], &B[(long)bk * N + colBase + bn]);
    }
    asm volatile("cp.async.commit_group;\n");

    #pragma unroll 1
    for (int k0 = 0; k0 < KTOT; k0 += 16) {
        int buf = (k0 >> 4) & 1;
        // stage next tile into other buffer (in flight during compute)
        if (k0 + 16 < KTOT) {
            const float* a0 = &A[(rowBase + am) * (long)KTOT + (k0 + 16) + ac];
            cp_async16(&As[buf ^ 1][am][ac], a0);
            cp_async16(&As[buf ^ 1][am + 64][ac], a0 + 64L * KTOT);
            cp_async16(&Bs[buf ^ 1][bk][bn],
                       &B[(long)(k0 + 16 + bk) * N + colBase + bn]);
        }
        asm volatile("cp.async.commit_group;\n");
        asm volatile("cp.async.wait_group 1;\n" ::: "memory");
        __syncthreads();

        #pragma unroll
        for (int ks = 0; ks < 2; ++ks) {
            int kb = ks * 8;
            unsigned af[2][4], bf[4][2];
            #pragma unroll
            for (int i = 0; i < 2; ++i) {
                int m0 = wm * 32 + i * 16;
                if (CVTA) {
                    af[i][0] = f2tf32(As[buf][m0 + r    ][kb + kq    ]);
                    af[i][1] = f2tf32(As[buf][m0 + r + 8][kb + kq    ]);
                    af[i][2] = f2tf32(As[buf][m0 + r    ][kb + kq + 4]);
                    af[i][3] = f2tf32(As[buf][m0 + r + 8][kb + kq + 4]);
                } else {
                    af[i][0] = __float_as_uint(As[buf][m0 + r    ][kb + kq    ]);
                    af[i][1] = __float_as_uint(As[buf][m0 + r + 8][kb + kq    ]);
                    af[i][2] = __float_as_uint(As[buf][m0 + r    ][kb + kq + 4]);
                    af[i][3] = __float_as_uint(As[buf][m0 + r + 8][kb + kq + 4]);
                }
            }
            #pragma unroll
            for (int j = 0; j < 4; ++j) {
                int n0 = wn * 32 + j * 8;
                bf[j][0] = __float_as_uint(Bs[buf][kb + kq    ][n0 + r]);
                bf[j][1] = __float_as_uint(Bs[buf][kb + kq + 4][n0 + r]);
            }
            #pragma unroll
            for (int i = 0; i < 2; ++i)
                #pragma unroll
                for (int j = 0; j < 4; ++j)
                    mma_tf32(c[i][j], af[i], bf[j]);
        }
        __syncthreads();
    }

    // ---- epilogue: c[i][j][e] -> C[row][col] ----
    #pragma unroll
    for (int i = 0; i < 2; ++i) {
        #pragma unroll
        for (int j = 0; j < 4; ++j) {
            long row0 = rowBase + wm * 32 + i * 16 + r;
            int  col0 = colBase + wn * 32 + j * 8 + 2 * kq;
            #pragma unroll
            for (int e = 0; e < 4; ++e) {
                long row = row0 + (e >> 1) * 8;
                int  col = col0 + (e & 1);
                float v = c[i][j][e] + bias[col];
                if (EPI == 1) v = round_tf32(gelu_tanh(v));  // feeds fc2 A only
                if (EPI == 2) v += res[row * N + col];
                C[row * N + col] = v;
            }
        }
    }
}

// ============================================================
// K_ln: out = LN(xin (+ addin)) * sc + bi
// ============================================================
__global__ __launch_bounds__(256)
void k_ln(const float* __restrict__ xin, const float* __restrict__ addin,
          const float* __restrict__ sc, const float* __restrict__ bi,
          float* __restrict__ out) {
    __shared__ float red[256];
    int t = threadIdx.x;
    for (int pp = 0; pp < 4; ++pp) {
        size_t p = (size_t)blockIdx.x * 4 + pp;
        float x = xin[p * 256 + t];
        if (addin) x += addin[p * 256 + t];
        float sum  = blk_sum256(x, red);
        float sum2 = blk_sum256(x * x, red);
        float mean = sum * (1.f / 256.f);
        float var  = sum2 * (1.f / 256.f) - mean * mean;
        out[p * 256 + t] = (x - mean) * rsqrtf(var + 1e-6f) * sc[t] + bi[t];
    }
}

// ============================================================
extern "C" void kernel_launch(void* const* d_in, const int* in_sizes, int n_in,
                              void* d_out, int out_size) {
    const float* hs    = (const float*)d_in[0];
    const float* emb   = (const float*)d_in[1];
    const float* Woff  = (const float*)d_in[2];
    const float* boff  = (const float*)d_in[3];
    const float* Wkvp  = (const float*)d_in[4];
    const float* bkvp  = (const float*)d_in[5];
    const float* Wq    = (const float*)d_in[6];
    const float* bq    = (const float*)d_in[7];
    const float* Wk    = (const float*)d_in[8];
    const float* bk    = (const float*)d_in[9];   (void)bk; // softmax-invariant, folded out
    const float* Wv    = (const float*)d_in[10];
    const float* bv    = (const float*)d_in[11];
    const float* Wo    = (const float*)d_in[12];
    const float* bo    = (const float*)d_in[13];
    const float* ln1s  = (const float*)d_in[14];
    const float* ln1b  = (const float*)d_in[15];
    const float* ln2s  = (const float*)d_in[16];
    const float* ln2b  = (const float*)d_in[17];
    const float* W1    = (const float*)d_in[18];
    const float* b1    = (const float*)d_in[19];
    const float* W2    = (const float*)d_in[20];
    const float* b2    = (const float*)d_in[21];
    float* out = (float*)d_out;

    float *p_Wqk, *p_Wvo, *p_W1r, *p_W2r, *p_bqk, *p_bvo;
    float *p_qk, *p_pkv, *p_o, *p_x, *p_h1, *p_y;
    cudaGetSymbolAddress((void**)&p_Wqk,  g_Wqk);
    cudaGetSymbolAddress((void**)&p_Wvo,  g_Wvo);
    cudaGetSymbolAddress((void**)&p_W1r,  g_W1r);
    cudaGetSymbolAddress((void**)&p_W2r,  g_W2r);
    cudaGetSymbolAddress((void**)&p_bqk,  g_bqk);
    cudaGetSymbolAddress((void**)&p_bvo,  g_bvo);
    cudaGetSymbolAddress((void**)&p_qk,   g_qk);
    cudaGetSymbolAddress((void**)&p_pkv,  g_pkv);
    cudaGetSymbolAddress((void**)&p_o,    g_o);
    cudaGetSymbolAddress((void**)&p_x,    g_x);
    cudaGetSymbolAddress((void**)&p_h1,   g_h1);
    cudaGetSymbolAddress((void**)&p_y,    g_y);

    // ---- one-time weight folding / rounding ----
    k_fold_qk<<<260, 256>>>(Wq, Wk, bq);
    k_fold_vo<<<1025, 256>>>(Wv, Wo, bv, bo);
    k_cvt_w<<<2048, 256>>>(W1, W2);

    // ---- main pipeline ----
    k_off<<<NPOS / 8, 256>>>(hs, Woff, boff);
    // qk = hs @ Wqk + bqk   [tf32, A needs cvt]
    gemm_tf32<256, 0, 1><<<dim3(64, 16), 256>>>(hs, p_Wqk, p_qk, 1024, p_bqk, nullptr);
    // fused: gather kv (SMEM) + scores + softmax + pkv  (4 pos/block)
    k_sample_core<<<NPOS / 4, 256>>>(emb, Wkvp, bkvp);
    // o = pkv @ Wvo + bvo   [tf32, both pre-rounded]
    gemm_tf32<1024, 0, 0><<<dim3(64, 4), 256>>>(p_pkv, p_Wvo, p_o, 256, p_bvo, nullptr);
    // x = LN1(hs + o)
    k_ln<<<NPOS / 4, 256>>>(hs, p_o, ln1s, ln1b, p_x);
    // h1 = gelu(x @ W1 + b1)   [tf32, A needs cvt]
    gemm_tf32<256, 1, 1><<<dim3(64, 16), 256>>>(p_x, p_W1r, p_h1, 1024, b1, nullptr);
    // y = x + h1 @ W2 + b2     [tf32, both pre-rounded]
    gemm_tf32<1024, 2, 0><<<dim3(64, 4), 256>>>(p_h1, p_W2r, p_y, 256, b2, p_x);
    // out = LN2(y)
    k_ln<<<NPOS / 4, 256>>>(p_y, nullptr, ln2s, ln2b, out);
}